// round 16
// baseline (speedup 1.0000x reference)
#include <cuda_runtime.h>
#include <cuda_bf16.h>
#include <cstdint>

#define BATCH  64
#define SEQ    512
#define INDIM  512
#define HID    1024
#define OUTDIM 512

// ---------------- device scratch ---------------------------------------------
__device__ float          g_xp[(size_t)BATCH * SEQ * HID];     // 128 MB x-projection
__device__ __nv_bfloat16  g_xhi[(size_t)BATCH * SEQ * INDIM];  // X split hi
__device__ __nv_bfloat16  g_xlo[(size_t)BATCH * SEQ * INDIM];  // X split lo
__device__ __nv_bfloat16  g_wihhi[(size_t)HID * INDIM];        // W_ih hi
__device__ __nv_bfloat16  g_wihlo[(size_t)HID * INDIM];        // W_ih lo
__device__ float          g_bias[HID];                         // b_ih + b_hh
__device__ __nv_bfloat16  g_whi[(size_t)HID * HID];            // W_hh hi
__device__ __nv_bfloat16  g_wlo[(size_t)HID * HID];            // W_hh lo
// per-producer flags: [bg][quarter][producer slot] each on its own 128B line
__device__ unsigned       g_flag[4][4][8][32];

// hidden state: bulk-copy-ready SWIZZLED image, quarter-major
// [par 2][bg 4][quarter 4][comp 2][slab 4][row 16 x 128 B]; within a row,
// 16B granule g stored at ((g ^ (row&7)) << 4) -> ldmatrix conflict-free.
#define IMG_PAR  262144u
#define IMG_BG   65536u
#define IMG_QTR  16384u
#define IMG_CMP  8192u
__device__ __align__(16) unsigned char g_himg[2 * 4 * IMG_BG];

// ---------------- mma / ldmatrix helpers -------------------------------------
__device__ __forceinline__ void ldsm4(uint32_t &r0, uint32_t &r1, uint32_t &r2,
                                      uint32_t &r3, uint32_t addr) {
    asm volatile("ldmatrix.sync.aligned.m8n8.x4.shared.b16 {%0,%1,%2,%3}, [%4];"
                 : "=r"(r0), "=r"(r1), "=r"(r2), "=r"(r3) : "r"(addr));
}
__device__ __forceinline__ void mma16816(float* d, uint32_t a0, uint32_t a1,
                                         uint32_t a2, uint32_t a3,
                                         uint32_t b0, uint32_t b1) {
    asm volatile(
        "mma.sync.aligned.m16n8k16.row.col.f32.bf16.bf16.f32 "
        "{%0,%1,%2,%3},{%4,%5,%6,%7},{%8,%9},{%0,%1,%2,%3};"
        : "+f"(d[0]), "+f"(d[1]), "+f"(d[2]), "+f"(d[3])
        : "r"(a0), "r"(a1), "r"(a2), "r"(a3), "r"(b0), "r"(b1));
}
__device__ __forceinline__ void split_bf16(float v, __nv_bfloat16 &hi, __nv_bfloat16 &lo) {
    hi = __float2bfloat16(v);
    lo = __float2bfloat16(v - __bfloat162float(hi));
}
__device__ __forceinline__ void mbar_wait(uint32_t mbar, unsigned phase) {
    uint32_t done;
    asm volatile(
        "{\n\t.reg .pred p;\n\t"
        "mbarrier.try_wait.parity.acquire.cta.shared::cta.b64 p, [%1], %2;\n\t"
        "selp.b32 %0, 1, 0, p;\n\t}"
        : "=r"(done) : "r"(mbar), "r"(phase) : "memory");
    if (!done) {
        asm volatile(
            "{\n\t.reg .pred P1;\n\t"
            "W%=:\n\t"
            "mbarrier.try_wait.parity.acquire.cta.shared::cta.b64 P1, [%0], %1, 0x989680;\n\t"
            "@P1 bra.uni D%=;\n\t"
            "bra.uni W%=;\n\t"
            "D%=:\n\t}"
            :: "r"(mbar), "r"(phase) : "memory");
    }
}

// ---------------- init: zero hidden image + flags ----------------------------
__global__ void k_init() {
    int i = blockIdx.x * blockDim.x + threadIdx.x;    // 135168 threads
    if (i < 4096) ((unsigned*)g_flag)[i] = 0u;
    if (i < 131072) ((uint32_t*)g_himg)[i] = 0u;      // 512 KB
}

// ---------------- prep: split X, W_hh, W_ih; fold biases ---------------------
__global__ void k_prep(const float* __restrict__ X, const float* __restrict__ Whh,
                       const float* __restrict__ Wih, const float* __restrict__ bih,
                       const float* __restrict__ bhh) {
    int i = blockIdx.x * blockDim.x + threadIdx.x;    // 16777216 threads
    {
        __nv_bfloat16 hi, lo;
        split_bf16(X[i], hi, lo);
        g_xhi[i] = hi; g_xlo[i] = lo;
    }
    if (i < HID * HID) {
        __nv_bfloat16 hi, lo;
        split_bf16(Whh[i], hi, lo);
        g_whi[i] = hi; g_wlo[i] = lo;
    }
    if (i < HID * INDIM) {
        __nv_bfloat16 hi, lo;
        split_bf16(Wih[i], hi, lo);
        g_wihhi[i] = hi; g_wihlo[i] = lo;
    }
    if (i < HID) g_bias[i] = bih[i] + bhh[i];
}

// ---------------- x_proj tensor-core GEMM (BM=256, BN=128, BK=64) ------------
#define XROW     144
#define XA_COMP  (256 * XROW)              // 36864
#define XA_STAGE (2 * XA_COMP)             // 73728
#define XB_COMP  (128 * XROW)              // 18432
#define XB_STAGE (2 * XB_COMP)             // 36864
#define XS_A     0
#define XS_B     (2 * XA_STAGE)            // 147456
#define XS_BYTES (XS_B + 2 * XB_STAGE)     // 221184

__device__ __forceinline__ void xp_stage(uint32_t smb, int s, int kt,
                                         int m0, int n0, int tid) {
    const int kb = kt * 64;
#pragma unroll
    for (int r = 0; r < 16; r++) {                   // A: 4096 granules
        int q = tid + 256 * r;
        int c = q >> 11, row = (q >> 3) & 255, kg = q & 7;
        const __nv_bfloat16* src =
            (c ? g_xlo : g_xhi) + (size_t)(m0 + row) * INDIM + kb + kg * 8;
        uint32_t dst = smb + XS_A + s * XA_STAGE + c * XA_COMP + row * XROW + kg * 16;
        asm volatile("cp.async.cg.shared.global [%0], [%1], 16;" :: "r"(dst), "l"(src));
    }
#pragma unroll
    for (int r = 0; r < 8; r++) {                    // B: 2048 granules
        int q = tid + 256 * r;
        int c = q >> 10, row = (q >> 3) & 127, kg = q & 7;
        const __nv_bfloat16* src =
            (c ? g_wihlo : g_wihhi) + (size_t)(n0 + row) * INDIM + kb + kg * 8;
        uint32_t dst = smb + XS_B + s * XB_STAGE + c * XB_COMP + row * XROW + kg * 16;
        asm volatile("cp.async.cg.shared.global [%0], [%1], 16;" :: "r"(dst), "l"(src));
    }
}

__global__ __launch_bounds__(256) void k_xproj()
{
    extern __shared__ char smc[];
    const uint32_t smb = (uint32_t)__cvta_generic_to_shared(smc);

    const int tid  = threadIdx.x;
    const int lane = tid & 31;
    const int w    = tid >> 5;
    const int wm   = (w >> 1) * 64;        // 4 m-groups x 64 rows
    const int wn   = (w & 1) * 64;         // 2 n-groups x 64 cols
    const int m0   = blockIdx.x * 256;
    const int n0   = blockIdx.y * 128;

    float D[4][8][4];                      // 64m x 64n per warp
#pragma unroll
    for (int i = 0; i < 4; i++)
#pragma unroll
        for (int j = 0; j < 8; j++)
#pragma unroll
            for (int r = 0; r < 4; r++) D[i][j][r] = 0.f;

    const uint32_t aoff = (wm + (lane & 15)) * XROW + (lane >> 4) * 16;
    uint32_t boff[4];
#pragma unroll
    for (int half = 0; half < 4; half++)
        boff[half] = (wn + half * 16 + (lane >> 4) * 8 + (lane & 7)) * XROW
                   + ((lane >> 3) & 1) * 16;

    xp_stage(smb, 0, 0, m0, n0, tid);
    asm volatile("cp.async.commit_group;");

    for (int kt = 0; kt < INDIM / 64; kt++) {
        const int s = kt & 1;
        if (kt + 1 < INDIM / 64) {
            xp_stage(smb, s ^ 1, kt + 1, m0, n0, tid);
            asm volatile("cp.async.commit_group;");
            asm volatile("cp.async.wait_group 1;");
        } else {
            asm volatile("cp.async.wait_group 0;");
        }
        __syncthreads();

        const uint32_t ah_b = smb + XS_A + s * XA_STAGE + aoff;
        const uint32_t al_b = ah_b + XA_COMP;
        const uint32_t bs_b = smb + XS_B + s * XB_STAGE;

#pragma unroll
        for (int ks = 0; ks < 4; ks++) {
            const uint32_t ka = ks * 32;
            uint32_t ah[4][4], al[4][4], bh[4][4], bl[4][4];
#pragma unroll
            for (int mi = 0; mi < 4; mi++) {
                ldsm4(ah[mi][0], ah[mi][1], ah[mi][2], ah[mi][3],
                      ah_b + mi * 16 * XROW + ka);
                ldsm4(al[mi][0], al[mi][1], al[mi][2], al[mi][3],
                      al_b + mi * 16 * XROW + ka);
            }
#pragma unroll
            for (int h = 0; h < 4; h++) {
                ldsm4(bh[h][0], bh[h][1], bh[h][2], bh[h][3], bs_b + boff[h] + ka);
                ldsm4(bl[h][0], bl[h][1], bl[h][2], bl[h][3],
                      bs_b + XB_COMP + boff[h] + ka);
            }
#pragma unroll
            for (int mi = 0; mi < 4; mi++)
#pragma unroll
                for (int o = 0; o < 8; o++) {
                    int h = o >> 1, p = (o & 1) * 2;
                    mma16816(D[mi][o], ah[mi][0], ah[mi][1], ah[mi][2], ah[mi][3],
                             bh[h][p], bh[h][p + 1]);
                    mma16816(D[mi][o], al[mi][0], al[mi][1], al[mi][2], al[mi][3],
                             bh[h][p], bh[h][p + 1]);
                    mma16816(D[mi][o], ah[mi][0], ah[mi][1], ah[mi][2], ah[mi][3],
                             bl[h][p], bl[h][p + 1]);
                }
        }
        __syncthreads();
    }

    const int rbase = lane >> 2;
    const int cbase = 2 * (lane & 3);
#pragma unroll
    for (int mi = 0; mi < 4; mi++)
#pragma unroll
        for (int o = 0; o < 8; o++) {
            int gm = m0 + wm + mi * 16 + rbase;
            int gn = n0 + wn + o * 8 + cbase;
            float2 b2 = *(const float2*)&g_bias[gn];
            float2 v;
            v.x = D[mi][o][0] + b2.x;
            v.y = D[mi][o][1] + b2.y;
            *(float2*)(g_xp + (size_t)gm * HID + gn) = v;
            v.x = D[mi][o][2] + b2.x;
            v.y = D[mi][o][3] + b2.y;
            *(float2*)(g_xp + (size_t)(gm + 8) * HID + gn) = v;
        }
}

// ---------------- recurrence: persistent tensor-core kernel ------------------
// 128 CTAs x 256 threads; 4 independent 32-CTA bg chains; exchange in 4
// QUARTERS. Per-PRODUCER release flags (distinct lines, no atomic
// serialization); orchestrator warps 0/2/4/6: lanes 0-7 poll one producer
// flag each, lane 0 issues the 16 KB bulk. Warp w <- (quarter q=w>>1,
// n-half h=w&1); 4-way reduction with contiguous j-pairs.
#define R_CTAS    128
#define R_THREADS 256

#define SM_WHI   0                       // [32][1032] bf16 (row 2064 B)
#define SM_WLO   66048
#define SM_HBUF  132096                  // 64 KB swizzled h image slice
#define SM_RED   197632                  // [4][16][34] f32
#define RED_Q    544
#define SM_MBAR  214528                  // 4 mbarriers
#define SM_BYTES 214784

__global__ __launch_bounds__(R_THREADS, 1) void k_recur()
{
    extern __shared__ char smc[];
    const uint32_t smb = (uint32_t)__cvta_generic_to_shared(smc);
    float* redf = (float*)(smc + SM_RED);

    const int tid  = threadIdx.x;
    const int lane = tid & 31;
    const int w    = tid >> 5;
    const int q    = w >> 1;        // k-quarter owned by this warp
    const int h    = w & 1;         // n-half (16 j-cols)
    const int jg   = blockIdx.x & 31;
    const int bgi  = blockIdx.x >> 5;
    const int cta_j0 = jg * 32;
    const int cta_b0 = bgi * 16;

    // this CTA's own flag (producer slot jg&7 of quarter jg>>3)
    unsigned* my_flag = &g_flag[bgi][jg >> 3][jg & 7][0];

    // ---- load W slice (32 j x 1024 k, hi+lo) into padded smem ----
#pragma unroll 8
    for (int it = 0; it < 32; it++) {
        int qq = tid + R_THREADS * it;
        int comp = qq >> 12, row = (qq >> 7) & 31, g = qq & 127;
        const __nv_bfloat16* src =
            (comp ? g_wlo : g_whi) + (size_t)(cta_j0 + row) * HID + g * 8;
        *(uint4*)(smc + (comp ? SM_WLO : SM_WHI) + row * 2064 + g * 16) =
            *(const uint4*)src;
    }
    __syncthreads();

    // ---- B (W) ldmatrix base: n16 rows at j-offset h*16 ----
    uint32_t b_base[2];
#pragma unroll
    for (int comp = 0; comp < 2; comp++)
        b_base[comp] = smb + (comp ? SM_WLO : SM_WHI)
            + (h * 16 + (lane >> 4) * 8 + (lane & 7)) * 2064
            + ((lane >> 3) & 1) * 16;

    // ---- hoist W fragments: 16 ktiles of quarter q, 2 comps ----
    uint32_t wf[16][2][4];
#pragma unroll
    for (int kt = 0; kt < 16; kt++)
#pragma unroll
        for (int comp = 0; comp < 2; comp++)
            ldsm4(wf[kt][comp][0], wf[kt][comp][1],
                  wf[kt][comp][2], wf[kt][comp][3],
                  b_base[comp] + q * 512 + kt * 32);

    // ---- mbarrier init (4) ----
    if (tid == 0) {
#pragma unroll
        for (int m = 0; m < 4; m++)
            asm volatile("mbarrier.init.shared.b64 [%0], %1;"
                         :: "r"(smb + SM_MBAR + m * 8), "r"(1u) : "memory");
        asm volatile("fence.proxy.async;" ::: "memory");
    }
    __syncthreads();

    // ---- A-fragment swizzled bases (quarter q) ----
    const int arow = lane & 15;
    const int ahi  = lane >> 4;
    const int axr  = arow & 7;
    uint32_t a_base[2];
#pragma unroll
    for (int comp = 0; comp < 2; comp++)
        a_base[comp] = smb + SM_HBUF + (uint32_t)q * IMG_QTR
                     + (uint32_t)comp * IMG_CMP + (uint32_t)arow * 128u;
    const uint32_t my_mbar = smb + SM_MBAR + (uint32_t)q * 8u;

    const int o0 = tid * 2;
    const int bl = o0 >> 5, jl = o0 & 31;
    // producer store address (quarter-major layout)
    const int pcol = cta_j0 + jl;
    const int pc   = pcol & 255;
    const uint32_t pbase = (uint32_t)bgi * IMG_BG
        + (uint32_t)(pcol >> 8) * IMG_QTR
        + (uint32_t)(pc >> 6) * 2048u
        + (uint32_t)bl * 128u
        + (uint32_t)((((pc >> 3) & 7) ^ (bl & 7)) << 4)
        + (uint32_t)((pc & 7) * 2);

    // orchestrator role: even warps, lanes 0-7; quarter = w>>1... but the
    // orchestrating warps must cover quarters 0-3 -> use warps 0,2,4,6 for
    // quarters 0,1,2,3 (warp 2m orchestrates quarter m).
    const bool is_orch = ((w & 1) == 0) && (lane < 8);
    const int  orch_q  = w >> 1;

    for (int t = 0; t < SEQ; t++) {
        const unsigned phase = (unsigned)(t & 1);
        const unsigned char* img = g_himg + (t & 1) * IMG_PAR + bgi * IMG_BG;

        // orchestrators: lanes 0-7 of warps 0/2/4/6; lane polls one producer
        if (is_orch) {
            if (t) {
                const unsigned need = (unsigned)t;
                const unsigned* fp = &g_flag[bgi][orch_q][lane][0];
                unsigned v;
                do {
                    asm volatile("ld.acquire.gpu.global.u32 %0, [%1];"
                                 : "=r"(v) : "l"(fp));
                } while (__any_sync(0x000000FFu, v < need));
            }
            if (lane == 0) {
                asm volatile("fence.proxy.async;" ::: "memory");
                const uint32_t mb = smb + SM_MBAR + orch_q * 8;
                asm volatile("mbarrier.arrive.expect_tx.shared.b64 _, [%0], %1;"
                             :: "r"(mb), "r"(IMG_QTR) : "memory");
                asm volatile(
                    "cp.async.bulk.shared::cluster.global.mbarrier::complete_tx::bytes"
                    " [%0], [%1], %2, [%3];"
                    :: "r"(smb + SM_HBUF + orch_q * IMG_QTR),
                       "l"(img + orch_q * IMG_QTR), "r"(IMG_QTR), "r"(mb)
                    : "memory");
            }
        }

        float2 xp = __ldg((const float2*)
            (g_xp + ((size_t)(cta_b0 + bl) * SEQ + t) * HID + cta_j0 + jl));

        float D1[2][4], D2[2][4];
#pragma unroll
        for (int i = 0; i < 2; i++)
#pragma unroll
            for (int j = 0; j < 4; j++) { D1[i][j] = 0.f; D2[i][j] = 0.f; }

        // wait only for THIS warp's quarter
        mbar_wait(my_mbar, phase);

#pragma unroll
        for (int kt = 0; kt < 16; kt++) {
            const uint32_t off = (uint32_t)(kt >> 2) * 2048u
                + (uint32_t)((((kt & 3) * 2 + ahi) ^ axr) << 4);
            uint32_t ah[4], al[4];
            ldsm4(ah[0], ah[1], ah[2], ah[3], a_base[0] + off);
            ldsm4(al[0], al[1], al[2], al[3], a_base[1] + off);
#pragma unroll
            for (int tt = 0; tt < 2; tt++)
                mma16816(D1[tt], ah[0], ah[1], ah[2], ah[3],
                         wf[kt][0][tt * 2], wf[kt][0][tt * 2 + 1]);
#pragma unroll
            for (int tt = 0; tt < 2; tt++)
                mma16816(D2[tt], al[0], al[1], al[2], al[3],
                         wf[kt][0][tt * 2], wf[kt][0][tt * 2 + 1]);
#pragma unroll
            for (int tt = 0; tt < 2; tt++)
                mma16816(D2[tt], ah[0], ah[1], ah[2], ah[3],
                         wf[kt][1][tt * 2], wf[kt][1][tt * 2 + 1]);
        }

        // ---- 4-way cross-quarter reduction via smem ----
#pragma unroll
        for (int tt = 0; tt < 2; tt++)
#pragma unroll
            for (int r = 0; r < 4; r++) {
                int row = (lane >> 2) + ((r >= 2) ? 8 : 0);
                int col = h * 16 + tt * 8 + 2 * (lane & 3) + (r & 1);
                redf[q * RED_Q + row * 34 + col] = D1[tt][r] + D2[tt][r];
            }
        __syncthreads();

        float v0 = 0.f, v1 = 0.f;
#pragma unroll
        for (int qq = 0; qq < 4; qq++) {
            float2 p = *(const float2*)&redf[qq * RED_Q + bl * 34 + jl];
            v0 += p.x;
            v1 += p.y;
        }
        v0 = tanhf(v0 + xp.x);
        v1 = tanhf(v1 + xp.y);

        __nv_bfloat16 h0, l0, h1, l1;
        split_bf16(v0, h0, l0);
        split_bf16(v1, h1, l1);
        unsigned char* hb = g_himg + ((t + 1) & 1) * IMG_PAR + pbase;
        __nv_bfloat162 ph; ph.x = h0; ph.y = h1;
        __nv_bfloat162 pl; pl.x = l0; pl.y = l1;
        *(__nv_bfloat162*)(hb)           = ph;
        *(__nv_bfloat162*)(hb + IMG_CMP) = pl;

        __syncthreads();
        if (tid == 0)
            asm volatile("st.release.gpu.global.u32 [%0], %1;"
                         :: "l"(my_flag), "r"((unsigned)(t + 1)) : "memory");
    }
}

// ---------------- output projection ------------------------------------------
__global__ __launch_bounds__(256) void k_out(
    const float* __restrict__ Who, const float* __restrict__ bho,
    float* __restrict__ out)
{
    const int lane = threadIdx.x & 31;
    const int gw   = blockIdx.x * 8 + (threadIdx.x >> 5);
    const int o0   = (gw >> 3) * 2;
    const int b0   = (gw & 7) * 8;

    const float4* W0 = (const float4*)(Who + (size_t)o0 * HID);
    const float4* W1 = (const float4*)(Who + (size_t)(o0 + 1) * HID);
    float4 wr0[8], wr1[8];
#pragma unroll
    for (int i = 0; i < 8; i++) {
        wr0[i] = W0[i * 32 + lane];
        wr1[i] = W1[i * 32 + lane];
    }
    float bias0 = __ldg(&bho[o0]), bias1 = __ldg(&bho[o0 + 1]);

    const int gran = (lane >> 1) & 7;     // granule within row
    const int bofs = (lane & 1) * 8;      // byte offset within granule (8B aligned)

#pragma unroll
    for (int b = 0; b < 8; b++) {
        const int bb = b0 + b;
        const int bg = bb >> 4, r = bb & 15;
        // final h (after step 511) lives in parity 0 of the swizzled image
        const unsigned char* base = g_himg + bg * IMG_BG + r * 128
                                  + ((gran ^ (r & 7)) << 4) + bofs;
        float a0 = 0.f, a1 = 0.f;
#pragma unroll
        for (int i = 0; i < 8; i++) {
            // k0 = lane*4 + i*128 -> quarter = i>>1, slab = (i&1)*2 + (lane>>4)
            const uint32_t off = (uint32_t)(i >> 1) * IMG_QTR
                               + (uint32_t)((i & 1) * 2 + (lane >> 4)) * 2048u;
            uint2 uh = *(const uint2*)(base + off);
            uint2 ul = *(const uint2*)(base + off + IMG_CMP);
            float2 f0 = __bfloat1622float2(*(__nv_bfloat162*)&uh.x);
            float2 f1 = __bfloat1622float2(*(__nv_bfloat162*)&uh.y);
            float2 g0 = __bfloat1622float2(*(__nv_bfloat162*)&ul.x);
            float2 g1 = __bfloat1622float2(*(__nv_bfloat162*)&ul.y);
            float hx = f0.x + g0.x, hy = f0.y + g0.y;
            float hz = f1.x + g1.x, hw = f1.y + g1.y;
            a0 += hx * wr0[i].x + hy * wr0[i].y + hz * wr0[i].z + hw * wr0[i].w;
            a1 += hx * wr1[i].x + hy * wr1[i].y + hz * wr1[i].z + hw * wr1[i].w;
        }
#pragma unroll
        for (int off = 16; off; off >>= 1) {
            a0 += __shfl_xor_sync(0xffffffffu, a0, off);
            a1 += __shfl_xor_sync(0xffffffffu, a1, off);
        }
        if (lane == 0) {
            out[(size_t)bb * OUTDIM + o0]     = a0 + bias0;
            out[(size_t)bb * OUTDIM + o0 + 1] = a1 + bias1;
        }
    }
}

// ---------------- launch ------------------------------------------------------
extern "C" void kernel_launch(void* const* d_in, const int* in_sizes, int n_in,
                              void* d_out, int out_size)
{
    (void)in_sizes; (void)n_in; (void)out_size;
    const float* X   = (const float*)d_in[0];
    const float* Wih = (const float*)d_in[1];
    const float* bih = (const float*)d_in[2];
    const float* Whh = (const float*)d_in[3];
    const float* bhh = (const float*)d_in[4];
    const float* Who = (const float*)d_in[5];
    const float* bho = (const float*)d_in[6];
    float* out = (float*)d_out;

    cudaFuncSetAttribute(k_xproj, cudaFuncAttributeMaxDynamicSharedMemorySize,
                         XS_BYTES);
    cudaFuncSetAttribute(k_recur, cudaFuncAttributeMaxDynamicSharedMemorySize,
                         SM_BYTES);

    k_init<<<528, 256>>>();
    k_prep<<<65536, 256>>>(X, Whh, Wih, bih, bhh);
    dim3 xg(BATCH * SEQ / 256, HID / 128);
    k_xproj<<<xg, 256, XS_BYTES>>>();
    k_recur<<<R_CTAS, R_THREADS, SM_BYTES>>>();
    k_out<<<256, 256>>>(Who, bho, out);
}

// round 17
// speedup vs baseline: 1.1020x; 1.1020x over previous
#include <cuda_runtime.h>
#include <cuda_bf16.h>
#include <cstdint>

#define BATCH  64
#define SEQ    512
#define INDIM  512
#define HID    1024
#define OUTDIM 512

// ---------------- device scratch ---------------------------------------------
__device__ float          g_xp[(size_t)BATCH * SEQ * HID];     // 128 MB x-projection
__device__ __nv_bfloat16  g_xhi[(size_t)BATCH * SEQ * INDIM];  // X split hi
__device__ __nv_bfloat16  g_xlo[(size_t)BATCH * SEQ * INDIM];  // X split lo
__device__ __nv_bfloat16  g_wihhi[(size_t)HID * INDIM];        // W_ih hi
__device__ __nv_bfloat16  g_wihlo[(size_t)HID * INDIM];        // W_ih lo
__device__ float          g_bias[HID];                         // b_ih + b_hh
__device__ __nv_bfloat16  g_whi[(size_t)HID * HID];            // W_hh hi
__device__ __nv_bfloat16  g_wlo[(size_t)HID * HID];            // W_hh lo
__device__ unsigned       g_sig[4][4][32];                     // [bg][quarter] counters

// hidden state: bulk-copy-ready SWIZZLED image, quarter-major
// [par 2][bg 4][quarter 4][comp 2][slab 4][row 16 x 128 B]; within a row,
// 16B granule g stored at ((g ^ (row&7)) << 4) -> ldmatrix conflict-free.
#define IMG_PAR  262144u
#define IMG_BG   65536u
#define IMG_QTR  16384u
#define IMG_CMP  8192u
__device__ __align__(16) unsigned char g_himg[2 * 4 * IMG_BG];

// ---------------- mma / ldmatrix helpers -------------------------------------
__device__ __forceinline__ void ldsm4(uint32_t &r0, uint32_t &r1, uint32_t &r2,
                                      uint32_t &r3, uint32_t addr) {
    asm volatile("ldmatrix.sync.aligned.m8n8.x4.shared.b16 {%0,%1,%2,%3}, [%4];"
                 : "=r"(r0), "=r"(r1), "=r"(r2), "=r"(r3) : "r"(addr));
}
__device__ __forceinline__ void mma16816(float* d, uint32_t a0, uint32_t a1,
                                         uint32_t a2, uint32_t a3,
                                         uint32_t b0, uint32_t b1) {
    asm volatile(
        "mma.sync.aligned.m16n8k16.row.col.f32.bf16.bf16.f32 "
        "{%0,%1,%2,%3},{%4,%5,%6,%7},{%8,%9},{%0,%1,%2,%3};"
        : "+f"(d[0]), "+f"(d[1]), "+f"(d[2]), "+f"(d[3])
        : "r"(a0), "r"(a1), "r"(a2), "r"(a3), "r"(b0), "r"(b1));
}
__device__ __forceinline__ void split_bf16(float v, __nv_bfloat16 &hi, __nv_bfloat16 &lo) {
    hi = __float2bfloat16(v);
    lo = __float2bfloat16(v - __bfloat162float(hi));
}
__device__ __forceinline__ void mbar_wait(uint32_t mbar, unsigned phase) {
    uint32_t done;
    asm volatile(
        "{\n\t.reg .pred p;\n\t"
        "mbarrier.try_wait.parity.acquire.cta.shared::cta.b64 p, [%1], %2;\n\t"
        "selp.b32 %0, 1, 0, p;\n\t}"
        : "=r"(done) : "r"(mbar), "r"(phase) : "memory");
    if (!done) {
        asm volatile(
            "{\n\t.reg .pred P1;\n\t"
            "W%=:\n\t"
            "mbarrier.try_wait.parity.acquire.cta.shared::cta.b64 P1, [%0], %1, 0x989680;\n\t"
            "@P1 bra.uni D%=;\n\t"
            "bra.uni W%=;\n\t"
            "D%=:\n\t}"
            :: "r"(mbar), "r"(phase) : "memory");
    }
}

// ---------------- init: zero hidden image + signals --------------------------
__global__ void k_init() {
    int i = blockIdx.x * blockDim.x + threadIdx.x;    // 131072 threads
    if (i < 512) ((unsigned*)g_sig)[i] = 0u;
    ((uint32_t*)g_himg)[i] = 0u;                      // 131072 u32 = 512 KB
}

// ---------------- prep: split X, W_hh, W_ih; fold biases ---------------------
__global__ void k_prep(const float* __restrict__ X, const float* __restrict__ Whh,
                       const float* __restrict__ Wih, const float* __restrict__ bih,
                       const float* __restrict__ bhh) {
    int i = blockIdx.x * blockDim.x + threadIdx.x;    // 16777216 threads
    {
        __nv_bfloat16 hi, lo;
        split_bf16(X[i], hi, lo);
        g_xhi[i] = hi; g_xlo[i] = lo;
    }
    if (i < HID * HID) {
        __nv_bfloat16 hi, lo;
        split_bf16(Whh[i], hi, lo);
        g_whi[i] = hi; g_wlo[i] = lo;
    }
    if (i < HID * INDIM) {
        __nv_bfloat16 hi, lo;
        split_bf16(Wih[i], hi, lo);
        g_wihhi[i] = hi; g_wihlo[i] = lo;
    }
    if (i < HID) g_bias[i] = bih[i] + bhh[i];
}

// ---------------- x_proj tensor-core GEMM (BM=256, BN=128, BK=64) ------------
#define XROW     144
#define XA_COMP  (256 * XROW)              // 36864
#define XA_STAGE (2 * XA_COMP)             // 73728
#define XB_COMP  (128 * XROW)              // 18432
#define XB_STAGE (2 * XB_COMP)             // 36864
#define XS_A     0
#define XS_B     (2 * XA_STAGE)            // 147456
#define XS_BYTES (XS_B + 2 * XB_STAGE)     // 221184

__device__ __forceinline__ void xp_stage(uint32_t smb, int s, int kt,
                                         int m0, int n0, int tid) {
    const int kb = kt * 64;
#pragma unroll
    for (int r = 0; r < 16; r++) {                   // A: 4096 granules
        int q = tid + 256 * r;
        int c = q >> 11, row = (q >> 3) & 255, kg = q & 7;
        const __nv_bfloat16* src =
            (c ? g_xlo : g_xhi) + (size_t)(m0 + row) * INDIM + kb + kg * 8;
        uint32_t dst = smb + XS_A + s * XA_STAGE + c * XA_COMP + row * XROW + kg * 16;
        asm volatile("cp.async.cg.shared.global [%0], [%1], 16;" :: "r"(dst), "l"(src));
    }
#pragma unroll
    for (int r = 0; r < 8; r++) {                    // B: 2048 granules
        int q = tid + 256 * r;
        int c = q >> 10, row = (q >> 3) & 127, kg = q & 7;
        const __nv_bfloat16* src =
            (c ? g_wihlo : g_wihhi) + (size_t)(n0 + row) * INDIM + kb + kg * 8;
        uint32_t dst = smb + XS_B + s * XB_STAGE + c * XB_COMP + row * XROW + kg * 16;
        asm volatile("cp.async.cg.shared.global [%0], [%1], 16;" :: "r"(dst), "l"(src));
    }
}

__global__ __launch_bounds__(256) void k_xproj()
{
    extern __shared__ char smc[];
    const uint32_t smb = (uint32_t)__cvta_generic_to_shared(smc);

    const int tid  = threadIdx.x;
    const int lane = tid & 31;
    const int w    = tid >> 5;
    const int wm   = (w >> 1) * 64;        // 4 m-groups x 64 rows
    const int wn   = (w & 1) * 64;         // 2 n-groups x 64 cols
    const int m0   = blockIdx.x * 256;
    const int n0   = blockIdx.y * 128;

    float D[4][8][4];                      // 64m x 64n per warp
#pragma unroll
    for (int i = 0; i < 4; i++)
#pragma unroll
        for (int j = 0; j < 8; j++)
#pragma unroll
            for (int r = 0; r < 4; r++) D[i][j][r] = 0.f;

    const uint32_t aoff = (wm + (lane & 15)) * XROW + (lane >> 4) * 16;
    uint32_t boff[4];
#pragma unroll
    for (int half = 0; half < 4; half++)
        boff[half] = (wn + half * 16 + (lane >> 4) * 8 + (lane & 7)) * XROW
                   + ((lane >> 3) & 1) * 16;

    xp_stage(smb, 0, 0, m0, n0, tid);
    asm volatile("cp.async.commit_group;");

    for (int kt = 0; kt < INDIM / 64; kt++) {
        const int s = kt & 1;
        if (kt + 1 < INDIM / 64) {
            xp_stage(smb, s ^ 1, kt + 1, m0, n0, tid);
            asm volatile("cp.async.commit_group;");
            asm volatile("cp.async.wait_group 1;");
        } else {
            asm volatile("cp.async.wait_group 0;");
        }
        __syncthreads();

        const uint32_t ah_b = smb + XS_A + s * XA_STAGE + aoff;
        const uint32_t al_b = ah_b + XA_COMP;
        const uint32_t bs_b = smb + XS_B + s * XB_STAGE;

#pragma unroll
        for (int ks = 0; ks < 4; ks++) {
            const uint32_t ka = ks * 32;
            uint32_t ah[4][4], al[4][4], bh[4][4], bl[4][4];
#pragma unroll
            for (int mi = 0; mi < 4; mi++) {
                ldsm4(ah[mi][0], ah[mi][1], ah[mi][2], ah[mi][3],
                      ah_b + mi * 16 * XROW + ka);
                ldsm4(al[mi][0], al[mi][1], al[mi][2], al[mi][3],
                      al_b + mi * 16 * XROW + ka);
            }
#pragma unroll
            for (int h = 0; h < 4; h++) {
                ldsm4(bh[h][0], bh[h][1], bh[h][2], bh[h][3], bs_b + boff[h] + ka);
                ldsm4(bl[h][0], bl[h][1], bl[h][2], bl[h][3],
                      bs_b + XB_COMP + boff[h] + ka);
            }
#pragma unroll
            for (int mi = 0; mi < 4; mi++)
#pragma unroll
                for (int o = 0; o < 8; o++) {
                    int h = o >> 1, p = (o & 1) * 2;
                    mma16816(D[mi][o], ah[mi][0], ah[mi][1], ah[mi][2], ah[mi][3],
                             bh[h][p], bh[h][p + 1]);
                    mma16816(D[mi][o], al[mi][0], al[mi][1], al[mi][2], al[mi][3],
                             bh[h][p], bh[h][p + 1]);
                    mma16816(D[mi][o], ah[mi][0], ah[mi][1], ah[mi][2], ah[mi][3],
                             bl[h][p], bl[h][p + 1]);
                }
        }
        __syncthreads();
    }

    const int rbase = lane >> 2;
    const int cbase = 2 * (lane & 3);
#pragma unroll
    for (int mi = 0; mi < 4; mi++)
#pragma unroll
        for (int o = 0; o < 8; o++) {
            int gm = m0 + wm + mi * 16 + rbase;
            int gn = n0 + wn + o * 8 + cbase;
            float2 b2 = *(const float2*)&g_bias[gn];
            float2 v;
            v.x = D[mi][o][0] + b2.x;
            v.y = D[mi][o][1] + b2.y;
            *(float2*)(g_xp + (size_t)gm * HID + gn) = v;
            v.x = D[mi][o][2] + b2.x;
            v.y = D[mi][o][3] + b2.y;
            *(float2*)(g_xp + (size_t)(gm + 8) * HID + gn) = v;
        }
}

// ---------------- recurrence: persistent tensor-core kernel ------------------
// (R15 verbatim — the best measured configuration.)
// 128 CTAs x 256 threads; 4 independent 32-CTA bg chains; exchange in 4
// QUARTERS with single red.release counters; orchestrator = lane 0 of warps
// 0/2/4/6, one counter each. Warp w <- (quarter q=w>>1, n-half h=w&1);
// W frags in registers; 4-way reduction with contiguous j-pairs.
#define R_CTAS    128
#define R_THREADS 256

#define SM_WHI   0                       // [32][1032] bf16 (row 2064 B)
#define SM_WLO   66048
#define SM_HBUF  132096                  // 64 KB swizzled h image slice
#define SM_RED   197632                  // [4][16][34] f32
#define RED_Q    544
#define SM_MBAR  214528                  // 4 mbarriers
#define SM_BYTES 214784

__global__ __launch_bounds__(R_THREADS, 1) void k_recur()
{
    extern __shared__ char smc[];
    const uint32_t smb = (uint32_t)__cvta_generic_to_shared(smc);
    float* redf = (float*)(smc + SM_RED);

    const int tid  = threadIdx.x;
    const int lane = tid & 31;
    const int w    = tid >> 5;
    const int q    = w >> 1;        // k-quarter owned by this warp
    const int h    = w & 1;         // n-half (16 j-cols)
    const int jg   = blockIdx.x & 31;
    const int bgi  = blockIdx.x >> 5;
    const int cta_j0 = jg * 32;
    const int cta_b0 = bgi * 16;

    unsigned* my_sig_out = &g_sig[bgi][jg >> 3][0];

    // ---- load W slice (32 j x 1024 k, hi+lo) into padded smem ----
#pragma unroll 8
    for (int it = 0; it < 32; it++) {
        int qq = tid + R_THREADS * it;
        int comp = qq >> 12, row = (qq >> 7) & 31, g = qq & 127;
        const __nv_bfloat16* src =
            (comp ? g_wlo : g_whi) + (size_t)(cta_j0 + row) * HID + g * 8;
        *(uint4*)(smc + (comp ? SM_WLO : SM_WHI) + row * 2064 + g * 16) =
            *(const uint4*)src;
    }
    __syncthreads();

    // ---- B (W) ldmatrix base: n16 rows at j-offset h*16 ----
    uint32_t b_base[2];
#pragma unroll
    for (int comp = 0; comp < 2; comp++)
        b_base[comp] = smb + (comp ? SM_WLO : SM_WHI)
            + (h * 16 + (lane >> 4) * 8 + (lane & 7)) * 2064
            + ((lane >> 3) & 1) * 16;

    // ---- hoist W fragments: 16 ktiles of quarter q, 2 comps ----
    uint32_t wf[16][2][4];
#pragma unroll
    for (int kt = 0; kt < 16; kt++)
#pragma unroll
        for (int comp = 0; comp < 2; comp++)
            ldsm4(wf[kt][comp][0], wf[kt][comp][1],
                  wf[kt][comp][2], wf[kt][comp][3],
                  b_base[comp] + q * 512 + kt * 32);

    // ---- mbarrier init (4) ----
    if (tid == 0) {
#pragma unroll
        for (int m = 0; m < 4; m++)
            asm volatile("mbarrier.init.shared.b64 [%0], %1;"
                         :: "r"(smb + SM_MBAR + m * 8), "r"(1u) : "memory");
        asm volatile("fence.proxy.async;" ::: "memory");
    }
    __syncthreads();

    // ---- A-fragment swizzled bases (quarter q) ----
    const int arow = lane & 15;
    const int ahi  = lane >> 4;
    const int axr  = arow & 7;
    uint32_t a_base[2];
#pragma unroll
    for (int comp = 0; comp < 2; comp++)
        a_base[comp] = smb + SM_HBUF + (uint32_t)q * IMG_QTR
                     + (uint32_t)comp * IMG_CMP + (uint32_t)arow * 128u;
    const uint32_t my_mbar = smb + SM_MBAR + (uint32_t)q * 8u;

    const int o0 = tid * 2;
    const int bl = o0 >> 5, jl = o0 & 31;
    // producer store address (quarter-major layout)
    const int pcol = cta_j0 + jl;
    const int pc   = pcol & 255;
    const uint32_t pbase = (uint32_t)bgi * IMG_BG
        + (uint32_t)(pcol >> 8) * IMG_QTR
        + (uint32_t)(pc >> 6) * 2048u
        + (uint32_t)bl * 128u
        + (uint32_t)((((pc >> 3) & 7) ^ (bl & 7)) << 4)
        + (uint32_t)((pc & 7) * 2);

    for (int t = 0; t < SEQ; t++) {
        const unsigned phase = (unsigned)(t & 1);
        const unsigned char* img = g_himg + (t & 1) * IMG_PAR + bgi * IMG_BG;

        // orchestrators: lane 0 of warps 0/2/4/6 handle quarter tid>>6
        if ((tid & 63) == 0) {
            const int qo = tid >> 6;
            if (t) {
                const unsigned need = 8u * (unsigned)t;
                const unsigned* sp = &g_sig[bgi][qo][0];
                unsigned v;
                do {
                    asm volatile("ld.acquire.gpu.global.u32 %0, [%1];"
                                 : "=r"(v) : "l"(sp));
                } while (v < need);
            }
            asm volatile("fence.proxy.async;" ::: "memory");
            const uint32_t mb = smb + SM_MBAR + qo * 8;
            asm volatile("mbarrier.arrive.expect_tx.shared.b64 _, [%0], %1;"
                         :: "r"(mb), "r"(IMG_QTR) : "memory");
            asm volatile(
                "cp.async.bulk.shared::cluster.global.mbarrier::complete_tx::bytes"
                " [%0], [%1], %2, [%3];"
                :: "r"(smb + SM_HBUF + qo * IMG_QTR), "l"(img + qo * IMG_QTR),
                   "r"(IMG_QTR), "r"(mb)
                : "memory");
        }

        float2 xp = __ldg((const float2*)
            (g_xp + ((size_t)(cta_b0 + bl) * SEQ + t) * HID + cta_j0 + jl));

        float D1[2][4], D2[2][4];
#pragma unroll
        for (int i = 0; i < 2; i++)
#pragma unroll
            for (int j = 0; j < 4; j++) { D1[i][j] = 0.f; D2[i][j] = 0.f; }

        // wait only for THIS warp's quarter
        mbar_wait(my_mbar, phase);

#pragma unroll
        for (int kt = 0; kt < 16; kt++) {
            const uint32_t off = (uint32_t)(kt >> 2) * 2048u
                + (uint32_t)((((kt & 3) * 2 + ahi) ^ axr) << 4);
            uint32_t ah[4], al[4];
            ldsm4(ah[0], ah[1], ah[2], ah[3], a_base[0] + off);
            ldsm4(al[0], al[1], al[2], al[3], a_base[1] + off);
#pragma unroll
            for (int tt = 0; tt < 2; tt++)
                mma16816(D1[tt], ah[0], ah[1], ah[2], ah[3],
                         wf[kt][0][tt * 2], wf[kt][0][tt * 2 + 1]);
#pragma unroll
            for (int tt = 0; tt < 2; tt++)
                mma16816(D2[tt], al[0], al[1], al[2], al[3],
                         wf[kt][0][tt * 2], wf[kt][0][tt * 2 + 1]);
#pragma unroll
            for (int tt = 0; tt < 2; tt++)
                mma16816(D2[tt], ah[0], ah[1], ah[2], ah[3],
                         wf[kt][1][tt * 2], wf[kt][1][tt * 2 + 1]);
        }

        // ---- 4-way cross-quarter reduction via smem ----
#pragma unroll
        for (int tt = 0; tt < 2; tt++)
#pragma unroll
            for (int r = 0; r < 4; r++) {
                int row = (lane >> 2) + ((r >= 2) ? 8 : 0);
                int col = h * 16 + tt * 8 + 2 * (lane & 3) + (r & 1);
                redf[q * RED_Q + row * 34 + col] = D1[tt][r] + D2[tt][r];
            }
        __syncthreads();

        float v0 = 0.f, v1 = 0.f;
#pragma unroll
        for (int qq = 0; qq < 4; qq++) {
            float2 p = *(const float2*)&redf[qq * RED_Q + bl * 34 + jl];
            v0 += p.x;
            v1 += p.y;
        }
        v0 = tanhf(v0 + xp.x);
        v1 = tanhf(v1 + xp.y);

        __nv_bfloat16 h0, l0, h1, l1;
        split_bf16(v0, h0, l0);
        split_bf16(v1, h1, l1);
        unsigned char* hb = g_himg + ((t + 1) & 1) * IMG_PAR + pbase;
        __nv_bfloat162 ph; ph.x = h0; ph.y = h1;
        __nv_bfloat162 pl; pl.x = l0; pl.y = l1;
        *(__nv_bfloat162*)(hb)           = ph;
        *(__nv_bfloat162*)(hb + IMG_CMP) = pl;

        __syncthreads();
        if (tid == 0)
            asm volatile("red.release.gpu.global.add.u32 [%0], %1;"
                         :: "l"(my_sig_out), "r"(1u));
    }
}

// ---------------- output projection ------------------------------------------
__global__ __launch_bounds__(256) void k_out(
    const float* __restrict__ Who, const float* __restrict__ bho,
    float* __restrict__ out)
{
    const int lane = threadIdx.x & 31;
    const int gw   = blockIdx.x * 8 + (threadIdx.x >> 5);
    const int o0   = (gw >> 3) * 2;
    const int b0   = (gw & 7) * 8;

    const float4* W0 = (const float4*)(Who + (size_t)o0 * HID);
    const float4* W1 = (const float4*)(Who + (size_t)(o0 + 1) * HID);
    float4 wr0[8], wr1[8];
#pragma unroll
    for (int i = 0; i < 8; i++) {
        wr0[i] = W0[i * 32 + lane];
        wr1[i] = W1[i * 32 + lane];
    }
    float bias0 = __ldg(&bho[o0]), bias1 = __ldg(&bho[o0 + 1]);

    const int gran = (lane >> 1) & 7;     // granule within row
    const int bofs = (lane & 1) * 8;      // byte offset within granule (8B aligned)

#pragma unroll
    for (int b = 0; b < 8; b++) {
        const int bb = b0 + b;
        const int bg = bb >> 4, r = bb & 15;
        // final h (after step 511) lives in parity 0 of the swizzled image
        const unsigned char* base = g_himg + bg * IMG_BG + r * 128
                                  + ((gran ^ (r & 7)) << 4) + bofs;
        float a0 = 0.f, a1 = 0.f;
#pragma unroll
        for (int i = 0; i < 8; i++) {
            // k0 = lane*4 + i*128 -> quarter = i>>1, slab = (i&1)*2 + (lane>>4)
            const uint32_t off = (uint32_t)(i >> 1) * IMG_QTR
                               + (uint32_t)((i & 1) * 2 + (lane >> 4)) * 2048u;
            uint2 uh = *(const uint2*)(base + off);
            uint2 ul = *(const uint2*)(base + off + IMG_CMP);
            float2 f0 = __bfloat1622float2(*(__nv_bfloat162*)&uh.x);
            float2 f1 = __bfloat1622float2(*(__nv_bfloat162*)&uh.y);
            float2 g0 = __bfloat1622float2(*(__nv_bfloat162*)&ul.x);
            float2 g1 = __bfloat1622float2(*(__nv_bfloat162*)&ul.y);
            float hx = f0.x + g0.x, hy = f0.y + g0.y;
            float hz = f1.x + g1.x, hw = f1.y + g1.y;
            a0 += hx * wr0[i].x + hy * wr0[i].y + hz * wr0[i].z + hw * wr0[i].w;
            a1 += hx * wr1[i].x + hy * wr1[i].y + hz * wr1[i].z + hw * wr1[i].w;
        }
#pragma unroll
        for (int off = 16; off; off >>= 1) {
            a0 += __shfl_xor_sync(0xffffffffu, a0, off);
            a1 += __shfl_xor_sync(0xffffffffu, a1, off);
        }
        if (lane == 0) {
            out[(size_t)bb * OUTDIM + o0]     = a0 + bias0;
            out[(size_t)bb * OUTDIM + o0 + 1] = a1 + bias1;
        }
    }
}

// ---------------- launch ------------------------------------------------------
extern "C" void kernel_launch(void* const* d_in, const int* in_sizes, int n_in,
                              void* d_out, int out_size)
{
    (void)in_sizes; (void)n_in; (void)out_size;
    const float* X   = (const float*)d_in[0];
    const float* Wih = (const float*)d_in[1];
    const float* bih = (const float*)d_in[2];
    const float* Whh = (const float*)d_in[3];
    const float* bhh = (const float*)d_in[4];
    const float* Who = (const float*)d_in[5];
    const float* bho = (const float*)d_in[6];
    float* out = (float*)d_out;

    cudaFuncSetAttribute(k_xproj, cudaFuncAttributeMaxDynamicSharedMemorySize,
                         XS_BYTES);
    cudaFuncSetAttribute(k_recur, cudaFuncAttributeMaxDynamicSharedMemorySize,
                         SM_BYTES);

    k_init<<<512, 256>>>();
    k_prep<<<65536, 256>>>(X, Whh, Wih, bih, bhh);
    dim3 xg(BATCH * SEQ / 256, HID / 128);
    k_xproj<<<xg, 256, XS_BYTES>>>();
    k_recur<<<R_CTAS, R_THREADS, SM_BYTES>>>();
    k_out<<<256, 256>>>(Who, bho, out);
}